// round 16
// baseline (speedup 1.0000x reference)
#include <cuda_runtime.h>
#include <cstdint>

#define NB 8
#define NN 1024
#define NC 1024
#define NH 16
#define HD 64
#define TOPK 256

// ---------------- scratch (static device globals; no allocation) ----------------
__device__ float g_qkv[(size_t)NB * NN * 3 * NC];     // 8192 x 3072
__device__ float g_attn[(size_t)NB * NH * NN * NN];   // 128 x 1024 x 1024
__device__ float g_x[(size_t)NB * NN * NC];
__device__ float g_y[(size_t)NB * NN * NC];
__device__ float g_sim[NB * NN];
__device__ float g_pooled[NB * NC];
__device__ float g_visinv[NB];
__device__ unsigned char g_mask[NB * NN];             // canonical 0/1 mask

// ---------------- mask canonicalization (auto-detect uint8 vs int32 bool) ----------------
__global__ __launch_bounds__(256) void mask_canon_kernel(const unsigned char* __restrict__ raw) {
    __shared__ int red[256];
    int tid = threadIdx.x;
    int any = 0;
    for (int i = tid; i < NB * NN; i += 256)
        if ((i & 3) != 0 && raw[i] != 0) any = 1;
    red[tid] = any;
    __syncthreads();
#pragma unroll
    for (int off = 128; off > 0; off >>= 1) {
        if (tid < off) red[tid] |= red[tid + off];
        __syncthreads();
    }
    int is_u8 = red[0];
    const int* raw32 = (const int*)raw;
    for (int i = tid; i < NB * NN; i += 256) {
        unsigned char v = is_u8 ? (raw[i] != 0) : (raw32[i] != 0);
        g_mask[i] = v;
    }
}

// ---------------- helpers ----------------
__device__ __forceinline__ unsigned fkey(float f) {
    unsigned u = __float_as_uint(f);
    return (u & 0x80000000u) ? ~u : (u | 0x80000000u);
}

__device__ __forceinline__ unsigned long long dup2(float f) {
    unsigned u = __float_as_uint(f);
    return ((unsigned long long)u << 32) | (unsigned long long)u;
}

// packed fp32x2 fma: d = a*b + d, lanewise on the two 32-bit halves
__device__ __forceinline__ void ffma2(unsigned long long& d, unsigned long long a,
                                      unsigned long long b) {
    asm("fma.rn.f32x2 %0, %1, %2, %3;" : "=l"(d) : "l"(a), "l"(b), "l"(d));
}

__device__ __forceinline__ float lo32(unsigned long long v) {
    return __uint_as_float((unsigned)v);
}
__device__ __forceinline__ float hi32(unsigned long long v) {
    return __uint_as_float((unsigned)(v >> 32));
}

__device__ __forceinline__ float bsum8(float v, float* red8, int lane, int wid) {
#pragma unroll
    for (int off = 16; off > 0; off >>= 1) v += __shfl_xor_sync(0xffffffffu, v, off);
    __syncthreads();
    if (lane == 0) red8[wid] = v;
    __syncthreads();
    float t = red8[0];
#pragma unroll
    for (int w = 1; w < 8; w++) t += red8[w];
    return t;
}

__device__ __forceinline__ float bmax8(float v, float* red8, int lane, int wid) {
#pragma unroll
    for (int off = 16; off > 0; off >>= 1) v = fmaxf(v, __shfl_xor_sync(0xffffffffu, v, off));
    __syncthreads();
    if (lane == 0) red8[wid] = v;
    __syncthreads();
    float t = red8[0];
#pragma unroll
    for (int w = 1; w < 8; w++) t = fmaxf(t, red8[w]);
    return t;
}

// Exact descending radix select over 1024 smem keys (256 threads) — used by pool_kernel.
__device__ __forceinline__ void radix_select_1024(const unsigned* sk, unsigned kwant,
                                                  unsigned* hist, unsigned* ss,
                                                  unsigned* sel, int tid) {
    if (tid == 0) { sel[0] = 0u; sel[1] = kwant; }
    unsigned pmask = 0u;
    __syncthreads();
    for (int shift = 24; shift >= 0; shift -= 8) {
        hist[tid] = 0u;
        __syncthreads();
        unsigned prefix = sel[0];
#pragma unroll
        for (int i = 0; i < 4; i++) {
            unsigned k = sk[tid + i * 256];
            if ((k & pmask) == prefix) atomicAdd(&hist[(k >> shift) & 255], 1u);
        }
        __syncthreads();
        ss[tid] = hist[tid];
        __syncthreads();
#pragma unroll
        for (int off = 1; off < 256; off <<= 1) {
            unsigned v = (tid + off < 256) ? ss[tid + off] : 0u;
            __syncthreads();
            ss[tid] += v;
            __syncthreads();
        }
        unsigned rem = sel[1];
        unsigned h = hist[tid];
        unsigned above = (tid < 255) ? ss[tid + 1] : 0u;
        __syncthreads();
        if (above < rem && above + h >= rem) {
            sel[0] = prefix | ((unsigned)tid << shift);
            sel[1] = rem - above;
        }
        pmask |= (0xFFu << shift);
        __syncthreads();
    }
}

// ---------------- generic fp32 GEMM via packed fma.f32x2: C = A*B + bias (+res) ----------------
// BM=128 BN=128 BK=16, 256 threads, 8x8 per thread. A stored dup'd as (a,a) 64-bit pairs;
// inner loop = 32 fma.rn.f32x2 per k (replaces 64 FFMA). Bit-identical arithmetic.
__global__ __launch_bounds__(256) void gemm_kernel(const float* __restrict__ A,
                                                   const float* __restrict__ B,
                                                   const float* __restrict__ bias,
                                                   const float* __restrict__ res,
                                                   float* __restrict__ C,
                                                   int M, int N, int K) {
    __shared__ unsigned long long As2[16][130];  // [k][m] duplicated pairs (16.6 KB)
    __shared__ float Bs[16][132];                // [k][n] (8.4 KB)
    int tid = threadIdx.x;
    int m0 = blockIdx.y * 128, n0 = blockIdx.x * 128;
    int ty = tid >> 4, tx = tid & 15;
    unsigned long long acc2[8][4];
#pragma unroll
    for (int r = 0; r < 8; r++)
#pragma unroll
        for (int c = 0; c < 4; c++) acc2[r][c] = 0ull;  // (0.f, 0.f)

    for (int k0 = 0; k0 < K; k0 += 16) {
#pragma unroll
        for (int i = 0; i < 2; i++) {
            int lin = tid + i * 256;
            int m = lin >> 2;
            int kq = (lin & 3) << 2;
            float4 v = *(const float4*)(A + (size_t)(m0 + m) * K + k0 + kq);
            As2[kq + 0][m] = dup2(v.x); As2[kq + 1][m] = dup2(v.y);
            As2[kq + 2][m] = dup2(v.z); As2[kq + 3][m] = dup2(v.w);
        }
#pragma unroll
        for (int i = 0; i < 2; i++) {
            int lin = tid + i * 256;
            int k = lin >> 5;
            int nq = (lin & 31) << 2;
            *(float4*)(&Bs[k][nq]) = *(const float4*)(B + (size_t)(k0 + k) * N + n0 + nq);
        }
        __syncthreads();
#pragma unroll
        for (int k = 0; k < 16; k++) {
            ulonglong2 ad2[4];
            ad2[0] = *(ulonglong2*)&As2[k][ty * 8 + 0];
            ad2[1] = *(ulonglong2*)&As2[k][ty * 8 + 2];
            ad2[2] = *(ulonglong2*)&As2[k][ty * 8 + 4];
            ad2[3] = *(ulonglong2*)&As2[k][ty * 8 + 6];
            ulonglong2 bp2[2];
            bp2[0] = *(ulonglong2*)&Bs[k][tx * 8];
            bp2[1] = *(ulonglong2*)&Bs[k][tx * 8 + 4];
            unsigned long long ad[8] = {ad2[0].x, ad2[0].y, ad2[1].x, ad2[1].y,
                                        ad2[2].x, ad2[2].y, ad2[3].x, ad2[3].y};
            unsigned long long bp[4] = {bp2[0].x, bp2[0].y, bp2[1].x, bp2[1].y};
#pragma unroll
            for (int r = 0; r < 8; r++)
#pragma unroll
                for (int c = 0; c < 4; c++) ffma2(acc2[r][c], ad[r], bp[c]);
        }
        __syncthreads();
    }
#pragma unroll
    for (int r = 0; r < 8; r++) {
        int m = m0 + ty * 8 + r;
#pragma unroll
        for (int p = 0; p < 2; p++) {
            int n = n0 + tx * 8 + p * 4;
            float4 v;
            v.x = lo32(acc2[r][p * 2 + 0]) + bias[n + 0];
            v.y = hi32(acc2[r][p * 2 + 0]) + bias[n + 1];
            v.z = lo32(acc2[r][p * 2 + 1]) + bias[n + 2];
            v.w = hi32(acc2[r][p * 2 + 1]) + bias[n + 3];
            if (res) {
                float4 rr = *(const float4*)(res + (size_t)m * N + n);
                v.x += rr.x; v.y += rr.y; v.z += rr.z; v.w += rr.w;
            }
            *(float4*)(C + (size_t)m * N + n) = v;
        }
    }
}

// ---------------- attn scores: 128x128 tile per block, BK=32 (unchanged R12) ----------------
__global__ __launch_bounds__(256) void attn_gemm_kernel(const float* __restrict__ qkv,
                                                        float* __restrict__ attn) {
    __shared__ float Qs[32][132];
    __shared__ float Ks[32][132];
    int tid = threadIdx.x;
    int q0 = blockIdx.x * 128, k0 = blockIdx.y * 128;
    int bh = blockIdx.z;
    int b = bh >> 4, h = bh & 15;
    size_t qbase = ((size_t)b * NN + q0) * 3072 + h * 64;
    size_t kbase = ((size_t)b * NN + k0) * 3072 + 1024 + h * 64;
    int ty = tid >> 4, tx = tid & 15;
    float acc[8][8];
#pragma unroll
    for (int r = 0; r < 8; r++)
#pragma unroll
        for (int c = 0; c < 8; c++) acc[r][c] = 0.f;

    for (int d0 = 0; d0 < 64; d0 += 32) {
#pragma unroll
        for (int i = 0; i < 4; i++) {
            int lin = tid + i * 256;
            int m = lin >> 3;
            int dq = (lin & 7) << 2;
            float4 qv = *(const float4*)(qkv + qbase + (size_t)m * 3072 + d0 + dq);
            Qs[dq + 0][m] = qv.x; Qs[dq + 1][m] = qv.y;
            Qs[dq + 2][m] = qv.z; Qs[dq + 3][m] = qv.w;
            float4 kv = *(const float4*)(qkv + kbase + (size_t)m * 3072 + d0 + dq);
            Ks[dq + 0][m] = kv.x; Ks[dq + 1][m] = kv.y;
            Ks[dq + 2][m] = kv.z; Ks[dq + 3][m] = kv.w;
        }
        __syncthreads();
#pragma unroll
        for (int d = 0; d < 32; d++) {
            float a[8], bb[8];
            *(float4*)&a[0] = *(float4*)&Qs[d][ty * 8];
            *(float4*)&a[4] = *(float4*)&Qs[d][ty * 8 + 4];
            *(float4*)&bb[0] = *(float4*)&Ks[d][tx * 8];
            *(float4*)&bb[4] = *(float4*)&Ks[d][tx * 8 + 4];
#pragma unroll
            for (int r = 0; r < 8; r++)
#pragma unroll
                for (int c = 0; c < 8; c++) acc[r][c] += a[r] * bb[c];
        }
        __syncthreads();
    }
    const float scale = 0.125f;
#pragma unroll
    for (int r = 0; r < 8; r++) {
#pragma unroll
        for (int c = 0; c < 8; c += 4) {
            float4 v;
            v.x = acc[r][c + 0] * scale; v.y = acc[r][c + 1] * scale;
            v.z = acc[r][c + 2] * scale; v.w = acc[r][c + 3] * scale;
            *(float4*)(attn + ((size_t)bh * NN + q0 + ty * 8 + r) * NN + k0 + tx * 8 + c) = v;
        }
    }
}

// ---------------- per-row top-256 + double softmax (R12 block version) ----------------
__global__ __launch_bounds__(256) void topk_softmax_kernel(float* __restrict__ attn) {
    int row = blockIdx.x;            // (b*16+h)*1024 + q
    int b = row >> 14;
    int tid = threadIdx.x;
    int lane = tid & 31, wid = tid >> 5;
    float* a = attn + (size_t)row * NN;
    __shared__ unsigned hist[256];
    __shared__ unsigned wtot[8];
    __shared__ float red8[8];
    __shared__ unsigned sel[3];
    __shared__ unsigned char tieflag[1024];
    __shared__ int s_partial;

    float v[4];
    unsigned k[4];
    unsigned char mk[4];
    float lm = -3.4e38f;
#pragma unroll
    for (int i = 0; i < 4; i++) {
        int idx = tid + i * 256;
        v[i] = a[idx];
        k[i] = fkey(v[i]);
        mk[i] = g_mask[b * NN + idx];
        lm = fmaxf(lm, v[i]);
    }
    if (tid == 0) { sel[0] = 0u; sel[1] = TOPK; }
    float m = bmax8(lm, red8, lane, wid);   // its syncs also publish sel[] init

    unsigned pmask = 0u;
#pragma unroll
    for (int shift = 24; shift >= 0; shift -= 8) {
        hist[tid] = 0u;
        unsigned prefix = sel[0];
        unsigned rem = sel[1];
        __syncthreads();
#pragma unroll
        for (int i = 0; i < 4; i++)
            if ((k[i] & pmask) == prefix) atomicAdd(&hist[(k[i] >> shift) & 255], 1u);
        __syncthreads();
        unsigned h = hist[tid];
        unsigned s = h;
#pragma unroll
        for (int off = 1; off < 32; off <<= 1) {
            unsigned n = __shfl_down_sync(0xffffffffu, s, off);
            if (lane + off < 32) s += n;
        }
        unsigned wt = __shfl_sync(0xffffffffu, s, 0);
        if (lane == 0) wtot[wid] = wt;
        __syncthreads();
        unsigned woff = 0;
        for (int w = wid + 1; w < 8; w++) woff += wtot[w];
        unsigned incl = s + woff;
        unsigned above = incl - h;
        if (above < rem && incl >= rem) {
            sel[0] = prefix | ((unsigned)tid << shift);
            sel[1] = rem - above;
            sel[2] = h;
        }
        pmask |= (0xFFu << shift);
        __syncthreads();
    }
    unsigned tk = sel[0], rem = sel[1], cnt_eq = sel[2];

    if (tid == 0) s_partial = (rem < cnt_eq);
    __syncthreads();
    int partial = s_partial;
    if (partial) {
        if (tid == 0) {
            unsigned taken = 0;
            for (int kk = 0; kk < 1024; kk++) {
                unsigned char f = (fkey(a[kk]) == tk && taken < rem) ? 1 : 0;
                tieflag[kk] = f;
                taken += f;
            }
        }
        __syncthreads();
    }

    bool inc[4];
#pragma unroll
    for (int i = 0; i < 4; i++)
        inc[i] = (k[i] > tk) || (k[i] == tk && (!partial || tieflag[tid + i * 256]));

    float lS = 0.f;
#pragma unroll
    for (int i = 0; i < 4; i++)
        if (inc[i]) lS += __expf(v[i] - m);
    float S = bsum8(lS, red8, lane, wid);
    float invS = 1.f / S;

    float lz = 0.f, e[4];
#pragma unroll
    for (int i = 0; i < 4; i++) {
        e[i] = mk[i] ? 0.f : (inc[i] ? __expf(__expf(v[i] - m) * invS) : 1.f);
        lz += e[i];
    }
    float Z = bsum8(lz, red8, lane, wid);
    float invZ = 1.f / Z;
#pragma unroll
    for (int i = 0; i < 4; i++)
        a[tid + i * 256] = e[i] * invZ;
}

// ---------------- AV: two heads per block -> 128x128 tile (unchanged R12) ----------------
__global__ __launch_bounds__(256) void av_gemm_kernel(const float* __restrict__ attn,
                                                      const float* __restrict__ qkv,
                                                      float* __restrict__ x) {
    __shared__ float Ws0[16][132];
    __shared__ float Ws1[16][132];
    __shared__ float Vs[16][132];
    int tid = threadIdx.x;
    int q0 = blockIdx.x * 128;
    int bhp = blockIdx.y;
    int b = bhp >> 3, hp = bhp & 7;
    int bh0 = b * 16 + hp * 2;
    int ty = tid >> 4, tx = tid & 15;
    const float* w0base = attn + (size_t)bh0 * NN * NN;
    const float* w1base = attn + (size_t)(bh0 + 1) * NN * NN;
    const float* vbase = qkv + (size_t)b * NN * 3072 + 2048 + hp * 128;

    float acc[8][8];
#pragma unroll
    for (int r = 0; r < 8; r++)
#pragma unroll
        for (int c = 0; c < 8; c++) acc[r][c] = 0.f;

    float (*Wsel)[132] = (tx < 8) ? Ws0 : Ws1;

    for (int kt = 0; kt < NN; kt += 16) {
#pragma unroll
        for (int i = 0; i < 2; i++) {
            int lin = tid + i * 256;
            int row = lin >> 2;
            int kq = (lin & 3) << 2;
            float4 w0 = *(const float4*)(w0base + (size_t)(q0 + row) * NN + kt + kq);
            Ws0[kq + 0][row] = w0.x; Ws0[kq + 1][row] = w0.y;
            Ws0[kq + 2][row] = w0.z; Ws0[kq + 3][row] = w0.w;
            float4 w1 = *(const float4*)(w1base + (size_t)(q0 + row) * NN + kt + kq);
            Ws1[kq + 0][row] = w1.x; Ws1[kq + 1][row] = w1.y;
            Ws1[kq + 2][row] = w1.z; Ws1[kq + 3][row] = w1.w;
            int vk = lin >> 5;
            int vd = (lin & 31) << 2;
            *(float4*)(&Vs[vk][vd]) = *(const float4*)(vbase + (size_t)(kt + vk) * 3072 + vd);
        }
        __syncthreads();
#pragma unroll
        for (int kk = 0; kk < 16; kk++) {
            float a[8], bb[8];
            *(float4*)&a[0] = *(float4*)&Wsel[kk][ty * 8];
            *(float4*)&a[4] = *(float4*)&Wsel[kk][ty * 8 + 4];
            *(float4*)&bb[0] = *(float4*)&Vs[kk][tx * 8];
            *(float4*)&bb[4] = *(float4*)&Vs[kk][tx * 8 + 4];
#pragma unroll
            for (int r = 0; r < 8; r++)
#pragma unroll
                for (int c = 0; c < 8; c++) acc[r][c] += a[r] * bb[c];
        }
        __syncthreads();
    }
#pragma unroll
    for (int r = 0; r < 8; r++) {
#pragma unroll
        for (int c = 0; c < 8; c += 4) {
            float4 v;
            v.x = acc[r][c + 0]; v.y = acc[r][c + 1];
            v.z = acc[r][c + 2]; v.w = acc[r][c + 3];
            *(float4*)(x + ((size_t)b * NN + q0 + ty * 8 + r) * NC + hp * 128 + tx * 8 + c) = v;
        }
    }
}

// ---------------- row layernorm over 1024 ----------------
__global__ __launch_bounds__(256) void ln_kernel(const float* __restrict__ in,
                                                 const float* __restrict__ g,
                                                 const float* __restrict__ bt,
                                                 float* __restrict__ out) {
    int row = blockIdx.x, tid = threadIdx.x;
    int lane = tid & 31, wid = tid >> 5;
    __shared__ float red8[8];
    const float* p = in + (size_t)row * 1024;
    float xv[4];
    float s = 0.f;
#pragma unroll
    for (int i = 0; i < 4; i++) {
        xv[i] = p[tid + i * 256];
        s += xv[i];
    }
    float mu = bsum8(s, red8, lane, wid) * (1.f / 1024.f);
    float vs = 0.f;
#pragma unroll
    for (int i = 0; i < 4; i++) {
        float d = xv[i] - mu;
        vs += d * d;
    }
    float var = bsum8(vs, red8, lane, wid) * (1.f / 1024.f);
    float rstd = rsqrtf(var + 1e-5f);
#pragma unroll
    for (int i = 0; i < 4; i++) {
        int idx = tid + i * 256;
        out[(size_t)row * 1024 + idx] = (xv[i] - mu) * rstd * g[idx] + bt[idx];
    }
}

// ---------------- vis token inverse norms ----------------
__global__ __launch_bounds__(256) void visnorm_kernel(const float* __restrict__ vis,
                                                      float* __restrict__ visinv) {
    int b = blockIdx.x, tid = threadIdx.x;
    int lane = tid & 31, wid = tid >> 5;
    __shared__ float red8[8];
    float s = 0.f;
#pragma unroll
    for (int i = 0; i < 4; i++) {
        float v = vis[b * 1024 + tid + i * 256];
        s += v * v;
    }
    float t = bsum8(s, red8, lane, wid);
    if (tid == 0) visinv[b] = 1.f / fmaxf(sqrtf(t), 1e-12f);
}

// ---------------- sim = sigmoid(beta + alpha * dot(vis_n, tf_n)), masked -> 0 ----------------
__global__ __launch_bounds__(256) void sim_kernel(const float* __restrict__ vis,
                                                  const float* __restrict__ tf,
                                                  const float* __restrict__ alpha,
                                                  const float* __restrict__ beta,
                                                  const float* __restrict__ visinv,
                                                  float* __restrict__ sim) {
    int bn = blockIdx.x;
    int b = bn >> 10;
    int tid = threadIdx.x;
    int lane = tid & 31, wid = tid >> 5;
    __shared__ float red8[8];
    const float* vrow = vis + b * 1024;
    const float* trow = tf + (size_t)bn * 1024;
    float tv[4], vv[4];
    float q = 0.f;
#pragma unroll
    for (int i = 0; i < 4; i++) {
        int idx = tid + i * 256;
        tv[i] = trow[idx];
        vv[i] = vrow[idx];
        q += tv[i] * tv[i];
    }
    q = bsum8(q, red8, lane, wid);
    float invt = 1.f / fmaxf(sqrtf(q), 1e-12f);
    float vi = visinv[b];
    float d = 0.f;
#pragma unroll
    for (int i = 0; i < 4; i++)
        d += (vv[i] * vi) * (tv[i] * invt);
    d = bsum8(d, red8, lane, wid);
    if (tid == 0) {
        float s;
        if (g_mask[bn]) {
            s = 0.f;  // sigmoid(-inf)
        } else {
            float val = beta[0] + alpha[0] * d;
            s = 1.f / (1.f + __expf(-val));
        }
        sim[bn] = s;
    }
}

// ---------------- top-256 sim pooling + txt_token add ----------------
__global__ __launch_bounds__(256) void pool_kernel(const float* __restrict__ sim,
                                                   const float* __restrict__ tf,
                                                   const float* __restrict__ txt,
                                                   float* __restrict__ pooled) {
    int b = blockIdx.x, tid = threadIdx.x;
    __shared__ unsigned sk[1024];
    __shared__ unsigned hist[256];
    __shared__ unsigned ss[256];
    __shared__ unsigned sel[2];
    __shared__ unsigned char tieflag[1024];
    __shared__ int s_partial;
    __shared__ unsigned sc[256];
    __shared__ short list[256];
#pragma unroll
    for (int i = 0; i < 4; i++) {
        int idx = tid + i * 256;
        sk[idx] = fkey(sim[b * 1024 + idx]);
    }
    __syncthreads();
    radix_select_1024(sk, TOPK, hist, ss, sel, tid);
    unsigned tk = sel[0];
    unsigned rem = sel[1];
    if (tid == 0) hist[0] = 0;
    __syncthreads();
#pragma unroll
    for (int i = 0; i < 4; i++)
        if (sk[tid + i * 256] == tk) atomicAdd(&hist[0], 1u);
    __syncthreads();
    unsigned cnt_eq = hist[0];
    if (tid == 0) {
        s_partial = (rem < cnt_eq);
        if (rem < cnt_eq) {  // ties (masked entries are all exactly 0): lowest indices win
            unsigned taken = 0;
            for (int k = 0; k < 1024; k++) {
                unsigned char f = (sk[k] == tk && taken < rem) ? 1 : 0;
                tieflag[k] = f;
                taken += f;
            }
        }
    }
    __syncthreads();
    int partial = s_partial;

    int base = tid * 4;
    unsigned cnt = 0;
    unsigned char f[4];
#pragma unroll
    for (int j = 0; j < 4; j++) {
        int k = base + j;
        unsigned kk = sk[k];
        bool inc = (kk > tk) || (kk == tk && (!partial || tieflag[k]));
        f[j] = inc;
        cnt += inc;
    }
    sc[tid] = cnt;
    __syncthreads();
#pragma unroll
    for (int off = 1; off < 256; off <<= 1) {
        unsigned v = (tid >= off) ? sc[tid - off] : 0u;
        __syncthreads();
        sc[tid] += v;
        __syncthreads();
    }
    unsigned pos = sc[tid] - cnt;
#pragma unroll
    for (int j = 0; j < 4; j++)
        if (f[j]) list[pos++] = (short)(base + j);
    __syncthreads();

    float acc[4] = {0.f, 0.f, 0.f, 0.f};
    for (int j = 0; j < TOPK; j++) {
        int n = list[j];
        const float* rrow = tf + ((size_t)b * 1024 + n) * 1024;
#pragma unroll
        for (int i = 0; i < 4; i++) acc[i] += rrow[tid + i * 256];
    }
#pragma unroll
    for (int i = 0; i < 4; i++) {
        int c = tid + i * 256;
        pooled[b * 1024 + c] = acc[i] * (1.f / 256.f) + txt[b * 1024 + c];
    }
}

// ---------------- tt = LN(pooled @ Wp1 + bp1) ----------------
__global__ __launch_bounds__(256) void final_kernel(const float* __restrict__ pooled,
                                                    const float* __restrict__ W,
                                                    const float* __restrict__ bias,
                                                    const float* __restrict__ g,
                                                    const float* __restrict__ bt,
                                                    float* __restrict__ out) {
    int b = blockIdx.x, tid = threadIdx.x;
    int lane = tid & 31, wid = tid >> 5;
    __shared__ float ts[1024];
    __shared__ float red8[8];
#pragma unroll
    for (int i = 0; i < 4; i++) ts[tid + i * 256] = pooled[b * 1024 + tid + i * 256];
    __syncthreads();
    float acc[4] = {0.f, 0.f, 0.f, 0.f};
#pragma unroll 4
    for (int c = 0; c < 1024; c++) {
        float tc = ts[c];
        const float* wr = W + (size_t)c * 1024 + tid;
        acc[0] += tc * wr[0];
        acc[1] += tc * wr[256];
        acc[2] += tc * wr[512];
        acc[3] += tc * wr[768];
    }
    float ys[4];
    float s = 0.f;
#pragma unroll
    for (int i = 0; i < 4; i++) {
        ys[i] = acc[i] + bias[tid + i * 256];
        s += ys[i];
    }
    float mu = bsum8(s, red8, lane, wid) * (1.f / 1024.f);
    float vs = 0.f;
#pragma unroll
    for (int i = 0; i < 4; i++) {
        float d = ys[i] - mu;
        vs += d * d;
    }
    float var = bsum8(vs, red8, lane, wid) * (1.f / 1024.f);
    float rstd = rsqrtf(var + 1e-5f);
#pragma unroll
    for (int i = 0; i < 4; i++) {
        int idx = tid + i * 256;
        out[b * 1024 + idx] = (ys[i] - mu) * rstd * g[idx] + bt[idx];
    }
}

// ---------------- host launch ----------------
extern "C" void kernel_launch(void* const* d_in, const int* in_sizes, int n_in,
                              void* d_out, int out_size) {
    const float* txt_token = (const float*)d_in[0];
    const float* text_features = (const float*)d_in[1];
    const unsigned char* text_mask = (const unsigned char*)d_in[2];
    const float* vis_token = (const float*)d_in[3];
    int o = (n_in > 4 && in_sizes[4] == 1) ? 1 : 0;
    const float* Wqkv = (const float*)d_in[4 + o];
    const float* bqkv = (const float*)d_in[5 + o];
    const float* Wp2 = (const float*)d_in[6 + o];
    const float* bp2 = (const float*)d_in[7 + o];
    const float* ln2_g = (const float*)d_in[8 + o];
    const float* ln2_b = (const float*)d_in[9 + o];
    const float* sim_alpha = (const float*)d_in[10 + o];
    const float* sim_beta = (const float*)d_in[11 + o];
    const float* Wp1 = (const float*)d_in[12 + o];
    const float* bp1 = (const float*)d_in[13 + o];
    const float* ln1_g = (const float*)d_in[14 + o];
    const float* ln1_b = (const float*)d_in[15 + o];

    float* out = (float*)d_out;
    float* tt = out;                 // (8,1,1024)
    float* tf = out + NB * NC;       // (8,1024,1024)

    float *qkv, *attn, *x, *y, *simv, *pooled, *visinv;
    cudaGetSymbolAddress((void**)&qkv, g_qkv);
    cudaGetSymbolAddress((void**)&attn, g_attn);
    cudaGetSymbolAddress((void**)&x, g_x);
    cudaGetSymbolAddress((void**)&y, g_y);
    cudaGetSymbolAddress((void**)&simv, g_sim);
    cudaGetSymbolAddress((void**)&pooled, g_pooled);
    cudaGetSymbolAddress((void**)&visinv, g_visinv);

    // 0. canonicalize mask
    mask_canon_kernel<<<1, 256>>>(text_mask);
    // 1. qkv = X @ Wqkv + bqkv   (fma.f32x2 GEMM)
    gemm_kernel<<<dim3(3072 / 128, 8192 / 128), 256>>>(text_features, Wqkv, bqkv, nullptr,
                                                       qkv, 8192, 3072, 1024);
    // 2. attn = Q K^T * scale
    attn_gemm_kernel<<<dim3(8, 8, 128), 256>>>(qkv, attn);
    // 3. top-256 + double softmax (block per row)
    topk_softmax_kernel<<<NB * NH * NN, 256>>>(attn);
    // 4. x = attn_w @ V  (two heads per block, 128x128 tile)
    av_gemm_kernel<<<dim3(8, 64), 256>>>(attn, qkv, x);
    // 5. y = x @ Wp2 + bp2 + text_features   (fma.f32x2 GEMM)
    gemm_kernel<<<dim3(1024 / 128, 8192 / 128), 256>>>(x, Wp2, bp2, text_features,
                                                       y, 8192, 1024, 1024);
    // 6. tf = layernorm(y)
    ln_kernel<<<8192, 256>>>(y, ln2_g, ln2_b, tf);
    // 7-8. sim
    visnorm_kernel<<<NB, 256>>>(vis_token, visinv);
    sim_kernel<<<NB * NN, 256>>>(vis_token, tf, sim_alpha, sim_beta, visinv, simv);
    // 9. pooled (+ txt_token)
    pool_kernel<<<NB, 256>>>(simv, tf, txt_token, pooled);
    // 10. tt = LN(pooled @ Wp1 + bp1)
    final_kernel<<<NB, 256>>>(pooled, Wp1, bp1, ln1_g, ln1_b, tt);
    (void)out_size;
}